// round 11
// baseline (speedup 1.0000x reference)
#include <cuda_runtime.h>
#include <math.h>
#include <stdint.h>

#define BATCH   4
#define SEQLEN  2048
#define DMODEL  1024
#define DINNER  2048
#define DSTATE  64
#define NHEADS  32
#define HEADDIM 64
#define CONVDIM 2176          // DINNER + 2*DSTATE
#define DIP     4256          // 2*DINNER + 2*DSTATE + NHEADS
#define MROWS   (BATCH*SEQLEN) // 8192
#define DTOFF   4224          // DINNER + CONVDIM

// ---- scratch (static device arrays; same footprint as passing builds) ----
__device__ float g_zx [2][MROWS][DIP];      // raw in-proj output
__device__ float g_xBC[2][MROWS][CONVDIM];  // ALIAS: tf32 in-proj W (before conv),
                                            //        tf32 out-proj W (after scan);
                                            // then post-conv+silu activations
__device__ float g_dt [2][NHEADS][MROWS];   // softplus(dt) TRANSPOSED (h-major)
__device__ float g_y  [2][MROWS][DINNER];   // ALIAS: tf32-rounded x (before scan);
                                            // then scan out -> gated/normed

__device__ __forceinline__ int fliprow(int m, int flip) {
    return flip ? ((m & ~(SEQLEN - 1)) | ((SEQLEN - 1) - (m & (SEQLEN - 1)))) : m;
}

__device__ __forceinline__ uint32_t f2tf32(float x) {
    uint32_t u;
    asm("cvt.rna.tf32.f32 %0, %1;" : "=r"(u) : "f"(x));
    return u;
}

// ---- packed f32x2 helpers (Blackwell) ----
typedef unsigned long long ull;
__device__ __forceinline__ ull pack2(float lo, float hi) {
    ull r; asm("mov.b64 %0, {%1, %2};" : "=l"(r) : "f"(lo), "f"(hi)); return r;
}
#define MUL2(d, a, b)    asm("mul.rn.f32x2 %0, %1, %2;" : "=l"(d) : "l"(a), "l"(b))
#define FMA2(d, a, b, c) asm("fma.rn.f32x2 %0, %1, %2, %3;" : "=l"(d) : "l"(a), "l"(b), "l"(c))
#define FMA2ACC(d, a, b) asm("fma.rn.f32x2 %0, %1, %2, %0;" : "+l"(d) : "l"(a), "l"(b))

// ---- cp.async ----
__device__ __forceinline__ void cp_async16(void* smem_dst, const float* gmem_src, int src_bytes) {
    uint32_t s = (uint32_t)__cvta_generic_to_shared(smem_dst);
    asm volatile("cp.async.cg.shared.global [%0], [%1], 16, %2;\n"
                 :: "r"(s), "l"(gmem_src), "r"(src_bytes));
}
__device__ __forceinline__ void cp_commit() { asm volatile("cp.async.commit_group;\n"); }
__device__ __forceinline__ void cp_wait0()  { asm volatile("cp.async.wait_group 0;\n"); }
__device__ __forceinline__ void cp_wait1()  { asm volatile("cp.async.wait_group 1;\n"); }

__device__ __forceinline__ void mma_16n8k8(float c[4], const uint32_t a[4], const uint32_t b[2]) {
    asm volatile("mma.sync.aligned.m16n8k8.row.col.f32.tf32.tf32.f32 "
                 "{%0,%1,%2,%3}, {%4,%5,%6,%7}, {%8,%9}, {%0,%1,%2,%3};"
                 : "+f"(c[0]), "+f"(c[1]), "+f"(c[2]), "+f"(c[3])
                 : "r"(a[0]), "r"(a[1]), "r"(a[2]), "r"(a[3]), "r"(b[0]), "r"(b[1]));
}

// ============================================================================
// Pre-round fp32 -> tf32-precision fp32 into aliased scratch regions.
// ============================================================================
__global__ void __launch_bounds__(256)
k_round(const float* __restrict__ src, int which, int n4)
{
    float* dst;
    switch (which) {
        case 0:  dst = &g_y[0][0][0]; break;
        case 1:  dst = &g_xBC[0][0][0]; break;
        case 2:  dst = &g_xBC[0][0][0] + (size_t)DIP * DMODEL; break;
        case 3:  dst = &g_xBC[0][0][0]; break;
        default: dst = &g_xBC[0][0][0] + (size_t)DMODEL * DINNER; break;
    }
    const int i = blockIdx.x * blockDim.x + threadIdx.x;
    if (i < n4) {
        float4 v = ((const float4*)src)[i];
        v.x = __uint_as_float(f2tf32(v.x));
        v.y = __uint_as_float(f2tf32(v.y));
        v.z = __uint_as_float(f2tf32(v.z));
        v.w = __uint_as_float(f2tf32(v.w));
        ((float4*)dst)[i] = v;
    }
}

// ============================================================================
// tf32 tensor-core GEMM core: CTA 128 threads = 4 warps (2x2), warp tile 64x64,
// CTA tile 128x128, BK=16, 2-stage cp.async. 3 CTAs/SM (12 warps) so the smem
// crossbar and tensor pipe overlap across CTAs.
// ============================================================================
#define SPITCH 20
#define GEMM_SMEM ((2 * 128 * SPITCH * 2) * 4)   // A + B, 2 stages: 40960 B

struct GemmFrag {
    float acc[4][8][4];
    __device__ __forceinline__ void zero() {
        #pragma unroll
        for (int mt = 0; mt < 4; mt++)
            #pragma unroll
            for (int nt = 0; nt < 8; nt++)
                #pragma unroll
                for (int c = 0; c < 4; c++) acc[mt][nt][c] = 0.f;
    }
};

__device__ __forceinline__ void gemm_compute_chunk(
    const float* As, const float* Bs, int wm, int wnn, int g, int tig, GemmFrag& F)
{
    #pragma unroll
    for (int kk = 0; kk < 16; kk += 8) {
        uint32_t af[4][4], bf[8][2];
        #pragma unroll
        for (int mt = 0; mt < 4; mt++) {
            const int m0 = wm + mt * 16 + g;
            af[mt][0] = __float_as_uint(As[m0 * SPITCH + kk + tig]);
            af[mt][1] = __float_as_uint(As[(m0 + 8) * SPITCH + kk + tig]);
            af[mt][2] = __float_as_uint(As[m0 * SPITCH + kk + tig + 4]);
            af[mt][3] = __float_as_uint(As[(m0 + 8) * SPITCH + kk + tig + 4]);
        }
        #pragma unroll
        for (int nt = 0; nt < 8; nt++) {
            const int n0 = wnn + nt * 8 + g;
            bf[nt][0] = __float_as_uint(Bs[n0 * SPITCH + kk + tig]);
            bf[nt][1] = __float_as_uint(Bs[n0 * SPITCH + kk + tig + 4]);
        }
        #pragma unroll
        for (int mt = 0; mt < 4; mt++)
            #pragma unroll
            for (int nt = 0; nt < 8; nt++)
                mma_16n8k8(F.acc[mt][nt], af[mt], bf[nt]);
    }
}

template<int N>
__device__ __forceinline__ void gemm_epilogue(
    GemmFrag& F, float* __restrict__ C,
    int mBase, int nBase, int wm, int wnn, int g, int tig)
{
    #pragma unroll
    for (int mt = 0; mt < 4; mt++) {
        const int m0 = mBase + wm + mt * 16 + g;
        float* crow0 = C + (size_t)m0 * N;
        float* crow1 = C + (size_t)(m0 + 8) * N;
        #pragma unroll
        for (int nt = 0; nt < 8; nt++) {
            const int n = nBase + wnn + nt * 8 + tig * 2;
            if (n < N) {
                *(float2*)(crow0 + n) = make_float2(F.acc[mt][nt][0], F.acc[mt][nt][1]);
                *(float2*)(crow1 + n) = make_float2(F.acc[mt][nt][2], F.acc[mt][nt][3]);
            }
        }
    }
}

// ---- in-proj: C[8192 x 4256] = xr @ W^T, K=1024 ----
__global__ void __launch_bounds__(128, 3)
k_inproj()
{
    extern __shared__ float sm[];
    float* AsBase = sm;                       // [2][128][SPITCH]
    float* BsBase = sm + 2 * 128 * SPITCH;    // [2][128][SPITCH]

    const int dir = blockIdx.z;
    const float* A = &g_y[0][0][0];
    const float* W = &g_xBC[0][0][0] + (size_t)dir * DIP * DMODEL;
    float* C = &g_zx[dir][0][0];
    constexpr int N = DIP, K = DMODEL;

    const int tid = threadIdx.x;
    const int mBase = blockIdx.y * 128;
    const int nBase = blockIdx.x * 128;

    const int am = fliprow(mBase + tid, dir);
    const float* Ar = A + (size_t)am * K;
    const int wn = nBase + tid;
    const float* Wr = W + (size_t)wn * K;
    const int wb = (wn < N) ? 16 : 0;

    const int lane = tid & 31;
    const int g = lane >> 2, tig = lane & 3;
    const int warp = tid >> 5;
    const int wm = (warp & 1) * 64, wnn = (warp >> 1) * 64;

    GemmFrag F; F.zero();

    auto issueChunk = [&](int ch) {
        const int st = ch & 1;
        const int ko = ch * 16;
        float* as = AsBase + st * (128 * SPITCH) + tid * SPITCH;
        float* bs = BsBase + st * (128 * SPITCH) + tid * SPITCH;
        #pragma unroll
        for (int j = 0; j < 4; j++) {
            cp_async16(as + j * 4, Ar + ko + j * 4, 16);
            cp_async16(bs + j * 4, Wr + ko + j * 4, wb);
        }
    };

    issueChunk(0); cp_commit();
    constexpr int NT = K / 16;
    #pragma unroll 1
    for (int kt = 0; kt < NT; kt++) {
        cp_wait0();
        __syncthreads();
        if (kt + 1 < NT) { issueChunk(kt + 1); cp_commit(); }
        const int st = kt & 1;
        gemm_compute_chunk(AsBase + st * (128 * SPITCH), BsBase + st * (128 * SPITCH),
                           wm, wnn, g, tig, F);
        __syncthreads();
    }
    gemm_epilogue<N>(F, C, mBase, nBase, wm, wnn, g, tig);
}

// ---- fused out-proj: out[m] = y0[m] @ W0^T + y1[flip m] @ W1^T, K=2*2048 ----
__global__ void __launch_bounds__(128, 3)
k_outproj(float* __restrict__ out)
{
    extern __shared__ float sm[];
    float* AsBase = sm;
    float* BsBase = sm + 2 * 128 * SPITCH;

    constexpr int N = DMODEL, K1 = DINNER;
    const float* W0 = &g_xBC[0][0][0];
    const float* W1 = W0 + (size_t)DMODEL * DINNER;

    const int tid = threadIdx.x;
    const int mBase = blockIdx.y * 128;
    const int nBase = blockIdx.x * 128;

    const int m0r = mBase + tid;
    const float* Ar0 = &g_y[0][m0r][0];
    const float* Ar1 = &g_y[1][fliprow(m0r, 1)][0];
    const int wn = nBase + tid;                 // always < N (1024 = 8*128)
    const float* Wr0 = W0 + (size_t)wn * K1;
    const float* Wr1 = W1 + (size_t)wn * K1;

    const int lane = tid & 31;
    const int g = lane >> 2, tig = lane & 3;
    const int warp = tid >> 5;
    const int wm = (warp & 1) * 64, wnn = (warp >> 1) * 64;

    GemmFrag F; F.zero();

    auto issueChunk = [&](int ch) {
        const int st = ch & 1;
        const int seg = (ch * 16 >= K1);
        const int ko = ch * 16 - (seg ? K1 : 0);
        const float* ar = seg ? Ar1 : Ar0;
        const float* wr = seg ? Wr1 : Wr0;
        float* as = AsBase + st * (128 * SPITCH) + tid * SPITCH;
        float* bs = BsBase + st * (128 * SPITCH) + tid * SPITCH;
        #pragma unroll
        for (int j = 0; j < 4; j++) {
            cp_async16(as + j * 4, ar + ko + j * 4, 16);
            cp_async16(bs + j * 4, wr + ko + j * 4, 16);
        }
    };

    issueChunk(0); cp_commit();
    constexpr int NT = 2 * K1 / 16;
    #pragma unroll 1
    for (int kt = 0; kt < NT; kt++) {
        cp_wait0();
        __syncthreads();
        if (kt + 1 < NT) { issueChunk(kt + 1); cp_commit(); }
        const int st = kt & 1;
        gemm_compute_chunk(AsBase + st * (128 * SPITCH), BsBase + st * (128 * SPITCH),
                           wm, wnn, g, tig, F);
        __syncthreads();
    }
    gemm_epilogue<N>(F, out, mBase, nBase, wm, wnn, g, tig);
}

// ============================================================================
// Depthwise causal conv (width 4) + bias + silu, fused with dt softplus.
// dt written TRANSPOSED: g_dt[dir][h][m].
// ============================================================================
__global__ void __launch_bounds__(256)
k_conv(const float* __restrict__ f_cw, const float* __restrict__ f_cb,
       const float* __restrict__ f_dtb,
       const float* __restrict__ b_cw, const float* __restrict__ b_cb,
       const float* __restrict__ b_dtb)
{
    const int c   = blockIdx.x * blockDim.x + threadIdx.x;
    const int m   = blockIdx.y;
    const int dir = blockIdx.z;
    const int l   = m & (SEQLEN - 1);

    if (c < CONVDIM) {
        const float* cw = dir ? b_cw : f_cw;
        const float* cb = dir ? b_cb : f_cb;
        float acc = cb[c];
        #pragma unroll
        for (int j = 0; j < 4; j++) {
            const int ls = l - 3 + j;
            if (ls >= 0)
                acc = fmaf(cw[c * 4 + j], g_zx[dir][m - 3 + j][DINNER + c], acc);
        }
        g_xBC[dir][m][c] = acc / (1.f + expf(-acc));
    } else if (c < CONVDIM + NHEADS) {
        const int h = c - CONVDIM;
        const float* dtb = dir ? b_dtb : f_dtb;
        const float v = g_zx[dir][m][DTOFF + h] + dtb[h];
        g_dt[dir][h][m] = (v > 20.f) ? v : log1pf(expf(v));
    }
}

// ============================================================================
// SSD scan v2 (unchanged from R7 passing build)
// ============================================================================
#define SCHUNK 8
__global__ void __launch_bounds__(64)
k_scan(const float* __restrict__ fA, const float* __restrict__ fD,
       const float* __restrict__ bA, const float* __restrict__ bD)
{
    const int h = blockIdx.x, b = blockIdx.y, dir = blockIdx.z;
    const int tid = threadIdx.x;
    const float Ah = -expf((dir ? bA : fA)[h]);
    const float Dh = (dir ? bD : fD)[h];
    const int mBase = b * SEQLEN;

    __shared__ __align__(16) float sX[2][SCHUNK][64];
    __shared__ __align__(16) float sB[2][SCHUNK][64];
    __shared__ __align__(16) float sC[2][SCHUNK][64];
    __shared__ __align__(16) float sDt[2][SCHUNK];

    ull S2[32];
    #pragma unroll
    for (int i = 0; i < 32; i++) S2[i] = 0ull;

    auto issue = [&](int buf, int chunk) {
        #pragma unroll
        for (int j = 0; j < 6; j++) {
            const int idx = tid + 64 * j;
            const int region = idx >> 7;
            const int r = idx & 127;
            const int t = r >> 4;
            const int o = (r & 15) * 4;
            const float* row = &g_xBC[dir][mBase + chunk * SCHUNK + t][0];
            const float* src;
            float* dst;
            if (region == 0)      { src = row + h * HEADDIM + o;     dst = &sX[buf][t][o]; }
            else if (region == 1) { src = row + DINNER + o;          dst = &sB[buf][t][o]; }
            else                  { src = row + DINNER + DSTATE + o; dst = &sC[buf][t][o]; }
            cp_async16(dst, src, 16);
        }
        if (tid < 2)
            cp_async16(&sDt[buf][tid * 4],
                       &g_dt[dir][h][mBase + chunk * SCHUNK + tid * 4], 16);
    };

    constexpr int NC = SEQLEN / SCHUNK;
    issue(0, 0);
    cp_commit();

    #pragma unroll 1
    for (int ch = 0; ch < NC; ch++) {
        const int buf = ch & 1;
        if (ch + 1 < NC) {
            issue(buf ^ 1, ch + 1);
            cp_commit();
            cp_wait1();
        } else {
            cp_wait0();
        }
        __syncthreads();

        #pragma unroll
        for (int t = 0; t < SCHUNK; t++) {
            const float dt = sDt[buf][t];
            const float dA = expf(dt * Ah);
            const float xp = sX[buf][t][tid];
            const float cf = dt * xp;
            const ull dA2 = pack2(dA, dA);
            const ull cf2 = pack2(cf, cf);

            ull y2[4] = {0ull, 0ull, 0ull, 0ull};
            #pragma unroll
            for (int q = 0; q < 16; q++) {
                const ulonglong2 bq = *(const ulonglong2*)&sB[buf][t][q * 4];
                const ulonglong2 cq = *(const ulonglong2*)&sC[buf][t][q * 4];
                ull tmp;
                MUL2(tmp, S2[2*q],   dA2); FMA2(S2[2*q],   cf2, bq.x, tmp);
                FMA2ACC(y2[(2*q)   & 3], S2[2*q],   cq.x);
                MUL2(tmp, S2[2*q+1], dA2); FMA2(S2[2*q+1], cf2, bq.y, tmp);
                FMA2ACC(y2[(2*q+1) & 3], S2[2*q+1], cq.y);
            }
            float ys = 0.f;
            #pragma unroll
            for (int a = 0; a < 4; a++) {
                uint32_t lo, hi;
                asm("mov.b64 {%0, %1}, %2;" : "=r"(lo), "=r"(hi) : "l"(y2[a]));
                ys += __uint_as_float(lo) + __uint_as_float(hi);
            }
            g_y[dir][mBase + ch * SCHUNK + t][h * HEADDIM + tid] = ys + Dh * xp;
        }
        __syncthreads();
    }
}

// ============================================================================
// Gate with silu(z), RMSNorm over DINNER, scale by norm_w. In-place on g_y.
// ============================================================================
__global__ void __launch_bounds__(256)
k_gate(const float* __restrict__ fnw, const float* __restrict__ bnw)
{
    const int m = blockIdx.x, dir = blockIdx.y;
    const int tid = threadIdx.x;
    const float* nw = dir ? bnw : fnw;

    const float4* y4p = (const float4*)&g_y[dir][m][0];
    const float4* z4p = (const float4*)&g_zx[dir][m][0];

    float4 v[2];
    float ss = 0.f;
    #pragma unroll
    for (int i = 0; i < 2; i++) {
        const int idx = tid + i * 256;
        const float4 y4 = y4p[idx];
        const float4 z4 = z4p[idx];
        float4 r;
        r.x = y4.x * (z4.x / (1.f + expf(-z4.x)));
        r.y = y4.y * (z4.y / (1.f + expf(-z4.y)));
        r.z = y4.z * (z4.z / (1.f + expf(-z4.z)));
        r.w = y4.w * (z4.w / (1.f + expf(-z4.w)));
        v[i] = r;
        ss += r.x * r.x + r.y * r.y + r.z * r.z + r.w * r.w;
    }
    __shared__ float red[8];
    #pragma unroll
    for (int o = 16; o > 0; o >>= 1) ss += __shfl_xor_sync(0xffffffffu, ss, o);
    if ((tid & 31) == 0) red[tid >> 5] = ss;
    __syncthreads();
    if (tid < 8) {
        float t = red[tid];
        #pragma unroll
        for (int o = 4; o > 0; o >>= 1) t += __shfl_xor_sync(0xffu, t, o);
        if (tid == 0) red[0] = t;
    }
    __syncthreads();
    const float scale = rsqrtf(red[0] / (float)DINNER + 1e-5f);

    float4* o4p = (float4*)&g_y[dir][m][0];
    #pragma unroll
    for (int i = 0; i < 2; i++) {
        const int idx = tid + i * 256;
        const float4 w4 = ((const float4*)nw)[idx];
        float4 r = v[i];
        r.x = __uint_as_float(f2tf32(r.x * scale * w4.x));
        r.y = __uint_as_float(f2tf32(r.y * scale * w4.y));
        r.z = __uint_as_float(f2tf32(r.z * scale * w4.z));
        r.w = __uint_as_float(f2tf32(r.w * scale * w4.w));
        o4p[idx] = r;
    }
}

// ============================================================================
extern "C" void kernel_launch(void* const* d_in, const int* in_sizes, int n_in,
                              void* d_out, int out_size)
{
    (void)in_sizes; (void)n_in; (void)out_size;
    const float* x      = (const float*)d_in[0];
    const float* f_in_w = (const float*)d_in[1];
    const float* f_cw   = (const float*)d_in[2];
    const float* f_cb   = (const float*)d_in[3];
    const float* f_dtb  = (const float*)d_in[4];
    const float* f_Al   = (const float*)d_in[5];
    const float* f_Dp   = (const float*)d_in[6];
    const float* f_nw   = (const float*)d_in[7];
    const float* f_ow   = (const float*)d_in[8];
    const float* b_in_w = (const float*)d_in[9];
    const float* b_cw   = (const float*)d_in[10];
    const float* b_cb   = (const float*)d_in[11];
    const float* b_dtb  = (const float*)d_in[12];
    const float* b_Al   = (const float*)d_in[13];
    const float* b_Dp   = (const float*)d_in[14];
    const float* b_nw   = (const float*)d_in[15];
    const float* b_ow   = (const float*)d_in[16];
    float* out = (float*)d_out;

    static int attr_done = 0;
    if (!attr_done) {
        cudaFuncSetAttribute(k_inproj,  cudaFuncAttributeMaxDynamicSharedMemorySize, GEMM_SMEM);
        cudaFuncSetAttribute(k_outproj, cudaFuncAttributeMaxDynamicSharedMemorySize, GEMM_SMEM);
        attr_done = 1;
    }

    const int nx  = MROWS * DMODEL / 4;
    const int nwi = DIP * DMODEL / 4;
    const int nwo = DMODEL * DINNER / 4;

    k_round<<<(nx  + 255) / 256, 256>>>(x,      0, nx);   // -> g_y alias
    k_round<<<(nwi + 255) / 256, 256>>>(f_in_w, 1, nwi);  // -> g_xBC alias
    k_round<<<(nwi + 255) / 256, 256>>>(b_in_w, 2, nwi);  // -> g_xBC alias

    dim3 gIn((DIP + 127) / 128, MROWS / 128, 2);          // 34 x 64 x 2
    k_inproj<<<gIn, 128, GEMM_SMEM>>>();

    dim3 gConv((CONVDIM + NHEADS + 255) / 256, MROWS, 2);
    k_conv<<<gConv, 256>>>(f_cw, f_cb, f_dtb, b_cw, b_cb, b_dtb);

    k_scan<<<dim3(NHEADS, BATCH, 2), HEADDIM>>>(f_Al, f_Dp, b_Al, b_Dp);

    // g_xBC fully consumed by k_scan -> reuse for rounded out-proj weights
    k_round<<<(nwo + 255) / 256, 256>>>(f_ow, 3, nwo);
    k_round<<<(nwo + 255) / 256, 256>>>(b_ow, 4, nwo);

    k_gate<<<dim3(MROWS, 2), 256>>>(f_nw, b_nw);

    dim3 gOut(DMODEL / 128, MROWS / 128);                 // 8 x 64
    k_outproj<<<gOut, 128, GEMM_SMEM>>>(out);
}

// round 12
// speedup vs baseline: 1.1808x; 1.1808x over previous
#include <cuda_runtime.h>
#include <math.h>
#include <stdint.h>

#define BATCH   4
#define SEQLEN  2048
#define DMODEL  1024
#define DINNER  2048
#define DSTATE  64
#define NHEADS  32
#define HEADDIM 64
#define CONVDIM 2176          // DINNER + 2*DSTATE
#define DIP     4256          // 2*DINNER + 2*DSTATE + NHEADS
#define MROWS   (BATCH*SEQLEN) // 8192
#define DTOFF   4224          // DINNER + CONVDIM

// ---- scratch (static device arrays; same footprint as passing builds) ----
__device__ float g_zx [2][MROWS][DIP];      // raw in-proj output
__device__ float g_xBC[2][MROWS][CONVDIM];  // ALIAS: tf32 in-proj W (before conv),
                                            //        tf32 out-proj W (after scan);
                                            // then post-conv+silu activations
__device__ float g_dt [2][NHEADS][MROWS];   // softplus(dt) TRANSPOSED (h-major)
__device__ float g_y  [2][MROWS][DINNER];   // ALIAS: tf32-rounded x (before scan);
                                            // then scan out -> gated/normed

__device__ __forceinline__ int fliprow(int m, int flip) {
    return flip ? ((m & ~(SEQLEN - 1)) | ((SEQLEN - 1) - (m & (SEQLEN - 1)))) : m;
}

__device__ __forceinline__ uint32_t f2tf32(float x) {
    uint32_t u;
    asm("cvt.rna.tf32.f32 %0, %1;" : "=r"(u) : "f"(x));
    return u;
}

// ---- packed f32x2 helpers (Blackwell) ----
typedef unsigned long long ull;
__device__ __forceinline__ ull pack2(float lo, float hi) {
    ull r; asm("mov.b64 %0, {%1, %2};" : "=l"(r) : "f"(lo), "f"(hi)); return r;
}
#define MUL2(d, a, b)    asm("mul.rn.f32x2 %0, %1, %2;" : "=l"(d) : "l"(a), "l"(b))
#define FMA2(d, a, b, c) asm("fma.rn.f32x2 %0, %1, %2, %3;" : "=l"(d) : "l"(a), "l"(b), "l"(c))
#define FMA2ACC(d, a, b) asm("fma.rn.f32x2 %0, %1, %2, %0;" : "+l"(d) : "l"(a), "l"(b))

// ---- cp.async ----
__device__ __forceinline__ void cp_async16(void* smem_dst, const float* gmem_src, int src_bytes) {
    uint32_t s = (uint32_t)__cvta_generic_to_shared(smem_dst);
    asm volatile("cp.async.cg.shared.global [%0], [%1], 16, %2;\n"
                 :: "r"(s), "l"(gmem_src), "r"(src_bytes));
}
__device__ __forceinline__ void cp_commit() { asm volatile("cp.async.commit_group;\n"); }
__device__ __forceinline__ void cp_wait0()  { asm volatile("cp.async.wait_group 0;\n"); }
__device__ __forceinline__ void cp_wait1()  { asm volatile("cp.async.wait_group 1;\n"); }

__device__ __forceinline__ void mma_16n8k8(float c[4], const uint32_t a[4], const uint32_t b[2]) {
    asm volatile("mma.sync.aligned.m16n8k8.row.col.f32.tf32.tf32.f32 "
                 "{%0,%1,%2,%3}, {%4,%5,%6,%7}, {%8,%9}, {%0,%1,%2,%3};"
                 : "+f"(c[0]), "+f"(c[1]), "+f"(c[2]), "+f"(c[3])
                 : "r"(a[0]), "r"(a[1]), "r"(a[2]), "r"(a[3]), "r"(b[0]), "r"(b[1]));
}

// ============================================================================
// Pre-round fp32 -> tf32-precision fp32 into aliased scratch regions.
// ============================================================================
__global__ void __launch_bounds__(256)
k_round(const float* __restrict__ src, int which, int n4)
{
    float* dst;
    switch (which) {
        case 0:  dst = &g_y[0][0][0]; break;
        case 1:  dst = &g_xBC[0][0][0]; break;
        case 2:  dst = &g_xBC[0][0][0] + (size_t)DIP * DMODEL; break;
        case 3:  dst = &g_xBC[0][0][0]; break;
        default: dst = &g_xBC[0][0][0] + (size_t)DMODEL * DINNER; break;
    }
    const int i = blockIdx.x * blockDim.x + threadIdx.x;
    if (i < n4) {
        float4 v = ((const float4*)src)[i];
        v.x = __uint_as_float(f2tf32(v.x));
        v.y = __uint_as_float(f2tf32(v.y));
        v.z = __uint_as_float(f2tf32(v.z));
        v.w = __uint_as_float(f2tf32(v.w));
        ((float4*)dst)[i] = v;
    }
}

// ============================================================================
// tf32 GEMM: CTA tile 128x256, 256 thr = 8 warps (2x4), warp tile 64x64
// (best crossbar ratio), 3-STAGE cp.async ring with ONE barrier per chunk
// (latency hidden by pipeline depth, not warp count). 92KB smem, 1 CTA/SM.
// ============================================================================
#define SPITCH 20
#define A_STG  (128 * SPITCH)
#define B_STG  (256 * SPITCH)
#define GEMM_SMEM ((3 * A_STG + 3 * B_STG) * 4)   // 92160 B

struct GemmFrag {
    float acc[4][8][4];
    __device__ __forceinline__ void zero() {
        #pragma unroll
        for (int mt = 0; mt < 4; mt++)
            #pragma unroll
            for (int nt = 0; nt < 8; nt++)
                #pragma unroll
                for (int c = 0; c < 4; c++) acc[mt][nt][c] = 0.f;
    }
};

__device__ __forceinline__ void gemm_compute_chunk(
    const float* As, const float* Bs, int wm, int wnn, int g, int tig, GemmFrag& F)
{
    #pragma unroll
    for (int kk = 0; kk < 16; kk += 8) {
        uint32_t af[4][4], bf[8][2];
        #pragma unroll
        for (int mt = 0; mt < 4; mt++) {
            const int m0 = wm + mt * 16 + g;
            af[mt][0] = __float_as_uint(As[m0 * SPITCH + kk + tig]);
            af[mt][1] = __float_as_uint(As[(m0 + 8) * SPITCH + kk + tig]);
            af[mt][2] = __float_as_uint(As[m0 * SPITCH + kk + tig + 4]);
            af[mt][3] = __float_as_uint(As[(m0 + 8) * SPITCH + kk + tig + 4]);
        }
        #pragma unroll
        for (int nt = 0; nt < 8; nt++) {
            const int n0 = wnn + nt * 8 + g;
            bf[nt][0] = __float_as_uint(Bs[n0 * SPITCH + kk + tig]);
            bf[nt][1] = __float_as_uint(Bs[n0 * SPITCH + kk + tig + 4]);
        }
        #pragma unroll
        for (int mt = 0; mt < 4; mt++)
            #pragma unroll
            for (int nt = 0; nt < 8; nt++)
                mma_16n8k8(F.acc[mt][nt], af[mt], bf[nt]);
    }
}

template<int N>
__device__ __forceinline__ void gemm_epilogue(
    GemmFrag& F, float* __restrict__ C,
    int mBase, int nBase, int wm, int wnn, int g, int tig)
{
    #pragma unroll
    for (int mt = 0; mt < 4; mt++) {
        const int m0 = mBase + wm + mt * 16 + g;
        float* crow0 = C + (size_t)m0 * N;
        float* crow1 = C + (size_t)(m0 + 8) * N;
        #pragma unroll
        for (int nt = 0; nt < 8; nt++) {
            const int n = nBase + wnn + nt * 8 + tig * 2;
            if (n < N) {
                *(float2*)(crow0 + n) = make_float2(F.acc[mt][nt][0], F.acc[mt][nt][1]);
                *(float2*)(crow1 + n) = make_float2(F.acc[mt][nt][2], F.acc[mt][nt][3]);
            }
        }
    }
}

// ---- in-proj: g_zx[dir] = xr @ W^T (rows flipped for dir=1), K=1024 ----
__global__ void __launch_bounds__(256, 1)
k_inproj()
{
    extern __shared__ float sm[];
    float* AsBase = sm;                 // [3][128][SPITCH]
    float* BsBase = sm + 3 * A_STG;     // [3][256][SPITCH]

    const int dir = blockIdx.z;
    const float* A = &g_y[0][0][0];
    const float* W = &g_xBC[0][0][0] + (size_t)dir * DIP * DMODEL;
    float* C = &g_zx[dir][0][0];
    constexpr int N = DIP, K = DMODEL;

    const int tid = threadIdx.x;
    const int mBase = blockIdx.y * 128;
    const int nBase = blockIdx.x * 256;

    const int r0 = tid >> 1;              // 0..127
    const int kc = (tid & 1) * 8;         // 0 or 8

    const int am = fliprow(mBase + r0, dir);
    const float* Ar  = A + (size_t)am * K + kc;
    const int wn0 = nBase + r0, wn1 = wn0 + 128;
    const float* Wr0 = W + (size_t)wn0 * K + kc;
    const float* Wr1 = W + (size_t)wn1 * K + kc;
    const int wb0 = (wn0 < N) ? 16 : 0;
    const int wb1 = (wn1 < N) ? 16 : 0;

    const int lane = tid & 31;
    const int g = lane >> 2, tig = lane & 3;
    const int warp = tid >> 5;
    const int wm = (warp & 1) * 64, wnn = (warp >> 1) * 64;

    GemmFrag F; F.zero();

    auto issueChunk = [&](int ch, int st) {
        const int ko = ch * 16;
        float* as  = AsBase + st * A_STG + r0 * SPITCH + kc;
        float* bs0 = BsBase + st * B_STG + r0 * SPITCH + kc;
        float* bs1 = bs0 + 128 * SPITCH;
        cp_async16(as,      Ar  + ko,     16);
        cp_async16(as + 4,  Ar  + ko + 4, 16);
        cp_async16(bs0,     Wr0 + ko,     wb0);
        cp_async16(bs0 + 4, Wr0 + ko + 4, wb0);
        cp_async16(bs1,     Wr1 + ko,     wb1);
        cp_async16(bs1 + 4, Wr1 + ko + 4, wb1);
    };

    issueChunk(0, 0); cp_commit();
    issueChunk(1, 1); cp_commit();

    constexpr int NT = K / 16;
    int stc = 0, sti = 2;
    #pragma unroll 1
    for (int kt = 0; kt < NT; kt++) {
        if (kt + 1 < NT) cp_wait1(); else cp_wait0();
        __syncthreads();
        if (kt + 2 < NT) {
            issueChunk(kt + 2, sti);
            cp_commit();
            sti = (sti == 2) ? 0 : sti + 1;
        }
        gemm_compute_chunk(AsBase + stc * A_STG, BsBase + stc * B_STG,
                           wm, wnn, g, tig, F);
        stc = (stc == 2) ? 0 : stc + 1;
    }
    gemm_epilogue<N>(F, C, mBase, nBase, wm, wnn, g, tig);
}

// ---- fused out-proj: out[m] = y0[m] @ W0^T + y1[flip m] @ W1^T, K=2*2048 ----
__global__ void __launch_bounds__(256, 1)
k_outproj(float* __restrict__ out)
{
    extern __shared__ float sm[];
    float* AsBase = sm;
    float* BsBase = sm + 3 * A_STG;

    constexpr int N = DMODEL, K1 = DINNER;
    const float* W0 = &g_xBC[0][0][0];
    const float* W1 = W0 + (size_t)DMODEL * DINNER;

    const int tid = threadIdx.x;
    const int mBase = blockIdx.y * 128;
    const int nBase = blockIdx.x * 256;

    const int r0 = tid >> 1;
    const int kc = (tid & 1) * 8;

    const int m0r = mBase + r0;
    const float* Ar0 = &g_y[0][m0r][kc];
    const float* Ar1 = &g_y[1][fliprow(m0r, 1)][kc];
    const int wn0 = nBase + r0, wn1 = wn0 + 128;   // always < 1024
    const float* Wr0a = W0 + (size_t)wn0 * K1 + kc;
    const float* Wr1a = W0 + (size_t)wn1 * K1 + kc;
    const float* Wr0b = W1 + (size_t)wn0 * K1 + kc;
    const float* Wr1b = W1 + (size_t)wn1 * K1 + kc;

    const int lane = tid & 31;
    const int g = lane >> 2, tig = lane & 3;
    const int warp = tid >> 5;
    const int wm = (warp & 1) * 64, wnn = (warp >> 1) * 64;

    GemmFrag F; F.zero();

    auto issueChunk = [&](int ch, int st) {
        const int seg = (ch * 16 >= K1);
        const int ko = ch * 16 - (seg ? K1 : 0);
        const float* ar  = seg ? Ar1  : Ar0;
        const float* w0r = seg ? Wr0b : Wr0a;
        const float* w1r = seg ? Wr1b : Wr1a;
        float* as  = AsBase + st * A_STG + r0 * SPITCH + kc;
        float* bs0 = BsBase + st * B_STG + r0 * SPITCH + kc;
        float* bs1 = bs0 + 128 * SPITCH;
        cp_async16(as,      ar  + ko,     16);
        cp_async16(as + 4,  ar  + ko + 4, 16);
        cp_async16(bs0,     w0r + ko,     16);
        cp_async16(bs0 + 4, w0r + ko + 4, 16);
        cp_async16(bs1,     w1r + ko,     16);
        cp_async16(bs1 + 4, w1r + ko + 4, 16);
    };

    issueChunk(0, 0); cp_commit();
    issueChunk(1, 1); cp_commit();

    constexpr int NT = 2 * K1 / 16;
    int stc = 0, sti = 2;
    #pragma unroll 1
    for (int kt = 0; kt < NT; kt++) {
        if (kt + 1 < NT) cp_wait1(); else cp_wait0();
        __syncthreads();
        if (kt + 2 < NT) {
            issueChunk(kt + 2, sti);
            cp_commit();
            sti = (sti == 2) ? 0 : sti + 1;
        }
        gemm_compute_chunk(AsBase + stc * A_STG, BsBase + stc * B_STG,
                           wm, wnn, g, tig, F);
        stc = (stc == 2) ? 0 : stc + 1;
    }
    gemm_epilogue<N>(F, out, mBase, nBase, wm, wnn, g, tig);
}

// ============================================================================
// Depthwise causal conv (width 4) + bias + silu, fused with dt softplus.
// dt written TRANSPOSED: g_dt[dir][h][m].
// ============================================================================
__global__ void __launch_bounds__(256)
k_conv(const float* __restrict__ f_cw, const float* __restrict__ f_cb,
       const float* __restrict__ f_dtb,
       const float* __restrict__ b_cw, const float* __restrict__ b_cb,
       const float* __restrict__ b_dtb)
{
    const int c   = blockIdx.x * blockDim.x + threadIdx.x;
    const int m   = blockIdx.y;
    const int dir = blockIdx.z;
    const int l   = m & (SEQLEN - 1);

    if (c < CONVDIM) {
        const float* cw = dir ? b_cw : f_cw;
        const float* cb = dir ? b_cb : f_cb;
        float acc = cb[c];
        #pragma unroll
        for (int j = 0; j < 4; j++) {
            const int ls = l - 3 + j;
            if (ls >= 0)
                acc = fmaf(cw[c * 4 + j], g_zx[dir][m - 3 + j][DINNER + c], acc);
        }
        g_xBC[dir][m][c] = acc / (1.f + expf(-acc));
    } else if (c < CONVDIM + NHEADS) {
        const int h = c - CONVDIM;
        const float* dtb = dir ? b_dtb : f_dtb;
        const float v = g_zx[dir][m][DTOFF + h] + dtb[h];
        g_dt[dir][h][m] = (v > 20.f) ? v : log1pf(expf(v));
    }
}

// ============================================================================
// SSD scan v2 (unchanged from R7 passing build)
// ============================================================================
#define SCHUNK 8
__global__ void __launch_bounds__(64)
k_scan(const float* __restrict__ fA, const float* __restrict__ fD,
       const float* __restrict__ bA, const float* __restrict__ bD)
{
    const int h = blockIdx.x, b = blockIdx.y, dir = blockIdx.z;
    const int tid = threadIdx.x;
    const float Ah = -expf((dir ? bA : fA)[h]);
    const float Dh = (dir ? bD : fD)[h];
    const int mBase = b * SEQLEN;

    __shared__ __align__(16) float sX[2][SCHUNK][64];
    __shared__ __align__(16) float sB[2][SCHUNK][64];
    __shared__ __align__(16) float sC[2][SCHUNK][64];
    __shared__ __align__(16) float sDt[2][SCHUNK];

    ull S2[32];
    #pragma unroll
    for (int i = 0; i < 32; i++) S2[i] = 0ull;

    auto issue = [&](int buf, int chunk) {
        #pragma unroll
        for (int j = 0; j < 6; j++) {
            const int idx = tid + 64 * j;
            const int region = idx >> 7;
            const int r = idx & 127;
            const int t = r >> 4;
            const int o = (r & 15) * 4;
            const float* row = &g_xBC[dir][mBase + chunk * SCHUNK + t][0];
            const float* src;
            float* dst;
            if (region == 0)      { src = row + h * HEADDIM + o;     dst = &sX[buf][t][o]; }
            else if (region == 1) { src = row + DINNER + o;          dst = &sB[buf][t][o]; }
            else                  { src = row + DINNER + DSTATE + o; dst = &sC[buf][t][o]; }
            cp_async16(dst, src, 16);
        }
        if (tid < 2)
            cp_async16(&sDt[buf][tid * 4],
                       &g_dt[dir][h][mBase + chunk * SCHUNK + tid * 4], 16);
    };

    constexpr int NC = SEQLEN / SCHUNK;
    issue(0, 0);
    cp_commit();

    #pragma unroll 1
    for (int ch = 0; ch < NC; ch++) {
        const int buf = ch & 1;
        if (ch + 1 < NC) {
            issue(buf ^ 1, ch + 1);
            cp_commit();
            cp_wait1();
        } else {
            cp_wait0();
        }
        __syncthreads();

        #pragma unroll
        for (int t = 0; t < SCHUNK; t++) {
            const float dt = sDt[buf][t];
            const float dA = expf(dt * Ah);
            const float xp = sX[buf][t][tid];
            const float cf = dt * xp;
            const ull dA2 = pack2(dA, dA);
            const ull cf2 = pack2(cf, cf);

            ull y2[4] = {0ull, 0ull, 0ull, 0ull};
            #pragma unroll
            for (int q = 0; q < 16; q++) {
                const ulonglong2 bq = *(const ulonglong2*)&sB[buf][t][q * 4];
                const ulonglong2 cq = *(const ulonglong2*)&sC[buf][t][q * 4];
                ull tmp;
                MUL2(tmp, S2[2*q],   dA2); FMA2(S2[2*q],   cf2, bq.x, tmp);
                FMA2ACC(y2[(2*q)   & 3], S2[2*q],   cq.x);
                MUL2(tmp, S2[2*q+1], dA2); FMA2(S2[2*q+1], cf2, bq.y, tmp);
                FMA2ACC(y2[(2*q+1) & 3], S2[2*q+1], cq.y);
            }
            float ys = 0.f;
            #pragma unroll
            for (int a = 0; a < 4; a++) {
                uint32_t lo, hi;
                asm("mov.b64 {%0, %1}, %2;" : "=r"(lo), "=r"(hi) : "l"(y2[a]));
                ys += __uint_as_float(lo) + __uint_as_float(hi);
            }
            g_y[dir][mBase + ch * SCHUNK + t][h * HEADDIM + tid] = ys + Dh * xp;
        }
        __syncthreads();
    }
}

// ============================================================================
// Gate with silu(z), RMSNorm over DINNER, scale by norm_w. In-place on g_y.
// ============================================================================
__global__ void __launch_bounds__(256)
k_gate(const float* __restrict__ fnw, const float* __restrict__ bnw)
{
    const int m = blockIdx.x, dir = blockIdx.y;
    const int tid = threadIdx.x;
    const float* nw = dir ? bnw : fnw;

    const float4* y4p = (const float4*)&g_y[dir][m][0];
    const float4* z4p = (const float4*)&g_zx[dir][m][0];

    float4 v[2];
    float ss = 0.f;
    #pragma unroll
    for (int i = 0; i < 2; i++) {
        const int idx = tid + i * 256;
        const float4 y4 = y4p[idx];
        const float4 z4 = z4p[idx];
        float4 r;
        r.x = y4.x * (z4.x / (1.f + expf(-z4.x)));
        r.y = y4.y * (z4.y / (1.f + expf(-z4.y)));
        r.z = y4.z * (z4.z / (1.f + expf(-z4.z)));
        r.w = y4.w * (z4.w / (1.f + expf(-z4.w)));
        v[i] = r;
        ss += r.x * r.x + r.y * r.y + r.z * r.z + r.w * r.w;
    }
    __shared__ float red[8];
    #pragma unroll
    for (int o = 16; o > 0; o >>= 1) ss += __shfl_xor_sync(0xffffffffu, ss, o);
    if ((tid & 31) == 0) red[tid >> 5] = ss;
    __syncthreads();
    if (tid < 8) {
        float t = red[tid];
        #pragma unroll
        for (int o = 4; o > 0; o >>= 1) t += __shfl_xor_sync(0xffu, t, o);
        if (tid == 0) red[0] = t;
    }
    __syncthreads();
    const float scale = rsqrtf(red[0] / (float)DINNER + 1e-5f);

    float4* o4p = (float4*)&g_y[dir][m][0];
    #pragma unroll
    for (int i = 0; i < 2; i++) {
        const int idx = tid + i * 256;
        const float4 w4 = ((const float4*)nw)[idx];
        float4 r = v[i];
        r.x = __uint_as_float(f2tf32(r.x * scale * w4.x));
        r.y = __uint_as_float(f2tf32(r.y * scale * w4.y));
        r.z = __uint_as_float(f2tf32(r.z * scale * w4.z));
        r.w = __uint_as_float(f2tf32(r.w * scale * w4.w));
        o4p[idx] = r;
    }
}

// ============================================================================
extern "C" void kernel_launch(void* const* d_in, const int* in_sizes, int n_in,
                              void* d_out, int out_size)
{
    (void)in_sizes; (void)n_in; (void)out_size;
    const float* x      = (const float*)d_in[0];
    const float* f_in_w = (const float*)d_in[1];
    const float* f_cw   = (const float*)d_in[2];
    const float* f_cb   = (const float*)d_in[3];
    const float* f_dtb  = (const float*)d_in[4];
    const float* f_Al   = (const float*)d_in[5];
    const float* f_Dp   = (const float*)d_in[6];
    const float* f_nw   = (const float*)d_in[7];
    const float* f_ow   = (const float*)d_in[8];
    const float* b_in_w = (const float*)d_in[9];
    const float* b_cw   = (const float*)d_in[10];
    const float* b_cb   = (const float*)d_in[11];
    const float* b_dtb  = (const float*)d_in[12];
    const float* b_Al   = (const float*)d_in[13];
    const float* b_Dp   = (const float*)d_in[14];
    const float* b_nw   = (const float*)d_in[15];
    const float* b_ow   = (const float*)d_in[16];
    float* out = (float*)d_out;

    static int attr_done = 0;
    if (!attr_done) {
        cudaFuncSetAttribute(k_inproj,  cudaFuncAttributeMaxDynamicSharedMemorySize, GEMM_SMEM);
        cudaFuncSetAttribute(k_outproj, cudaFuncAttributeMaxDynamicSharedMemorySize, GEMM_SMEM);
        attr_done = 1;
    }

    const int nx  = MROWS * DMODEL / 4;
    const int nwi = DIP * DMODEL / 4;
    const int nwo = DMODEL * DINNER / 4;

    k_round<<<(nx  + 255) / 256, 256>>>(x,      0, nx);   // -> g_y alias
    k_round<<<(nwi + 255) / 256, 256>>>(f_in_w, 1, nwi);  // -> g_xBC alias
    k_round<<<(nwi + 255) / 256, 256>>>(b_in_w, 2, nwi);  // -> g_xBC alias

    dim3 gIn((DIP + 255) / 256, MROWS / 128, 2);          // 17 x 64 x 2
    k_inproj<<<gIn, 256, GEMM_SMEM>>>();

    dim3 gConv((CONVDIM + NHEADS + 255) / 256, MROWS, 2);
    k_conv<<<gConv, 256>>>(f_cw, f_cb, f_dtb, b_cw, b_cb, b_dtb);

    k_scan<<<dim3(NHEADS, BATCH, 2), HEADDIM>>>(f_Al, f_Dp, b_Al, b_Dp);

    // g_xBC fully consumed by k_scan -> reuse for rounded out-proj weights
    k_round<<<(nwo + 255) / 256, 256>>>(f_ow, 3, nwo);
    k_round<<<(nwo + 255) / 256, 256>>>(b_ow, 4, nwo);

    k_gate<<<dim3(MROWS, 2), 256>>>(f_nw, b_nw);

    dim3 gOut(DMODEL / 256, MROWS / 128);                 // 4 x 64
    k_outproj<<<gOut, 256, GEMM_SMEM>>>(out);
}